// round 1
// baseline (speedup 1.0000x reference)
#include <cuda_runtime.h>
#include <math.h>

#define B_ROWS 131072
#define DIM    512
#define CTX    128
#define HID    2048
#define KIN    384      // D_M + CTX
#define S_MAX  5.0f

// Scratch (static device globals; no allocations in kernel_launch)
__device__ float g_h [(size_t)B_ROWS * HID];   // relu(st_in @ W1 + b1)
__device__ float g_st[(size_t)B_ROWS * DIM];   // h @ W2 + b2

#define BM 128
#define BN 64
#define BK 16
#define TM 8
#define TN 4
// 256 threads: 16 (ty, row groups of 8) x 16 (tx, col groups of 4)

// ---------------------------------------------------------------------------
// GEMM1: g_h[M, HID] = relu( A @ W1 + b1 ),  A[m,k] = (k<256 ? x[m,2k] : ctx[m,k-256])
// ---------------------------------------------------------------------------
__global__ __launch_bounds__(256)
void gemm1_kernel(const float* __restrict__ x,
                  const float* __restrict__ ctx,
                  const float* __restrict__ W1,
                  const float* __restrict__ b1)
{
    __shared__ float As[BM][BK];
    __shared__ float Bs[BK][BN];

    const int tid = threadIdx.x;
    const int tx  = tid & 15;
    const int ty  = tid >> 4;
    const int block_n = blockIdx.x * BN;
    const int block_m = blockIdx.y * BM;

    float acc[TM][TN];
#pragma unroll
    for (int i = 0; i < TM; i++)
#pragma unroll
        for (int j = 0; j < TN; j++) acc[i][j] = 0.0f;

    for (int k0 = 0; k0 < KIN; k0 += BK) {
        // Load A tile (gathered): 128x16, 8 elems/thread.
        // idx = i*256 + tid -> ml = idx/16, kl = idx%16 (consec. tid -> consec. k)
#pragma unroll
        for (int i = 0; i < 8; i++) {
            int idx = i * 256 + tid;
            int ml  = idx >> 4;
            int kl  = idx & 15;
            int gm  = block_m + ml;
            int gk  = k0 + kl;
            float v;
            if (gk < 256) v = x[(size_t)gm * DIM + 2 * gk];
            else          v = ctx[(size_t)gm * CTX + (gk - 256)];
            As[ml][kl] = v;
        }
        // Load B tile (W1): 16x64, one float4/thread
        {
            int kl = tid >> 4;
            int nl = (tid & 15) * 4;
            const float4 w = *(const float4*)&W1[(size_t)(k0 + kl) * HID + block_n + nl];
            *(float4*)&Bs[kl][nl] = w;
        }
        __syncthreads();

#pragma unroll
        for (int k = 0; k < BK; k++) {
            float4 b4 = *(float4*)&Bs[k][tx * 4];
            float a[TM];
#pragma unroll
            for (int i = 0; i < TM; i++) a[i] = As[ty * TM + i][k];
#pragma unroll
            for (int i = 0; i < TM; i++) {
                acc[i][0] = fmaf(a[i], b4.x, acc[i][0]);
                acc[i][1] = fmaf(a[i], b4.y, acc[i][1]);
                acc[i][2] = fmaf(a[i], b4.z, acc[i][2]);
                acc[i][3] = fmaf(a[i], b4.w, acc[i][3]);
            }
        }
        __syncthreads();
    }

    const float4 bias = *(const float4*)&b1[block_n + tx * 4];
#pragma unroll
    for (int i = 0; i < TM; i++) {
        int gm = block_m + ty * TM + i;
        float4 r;
        r.x = fmaxf(acc[i][0] + bias.x, 0.0f);
        r.y = fmaxf(acc[i][1] + bias.y, 0.0f);
        r.z = fmaxf(acc[i][2] + bias.z, 0.0f);
        r.w = fmaxf(acc[i][3] + bias.w, 0.0f);
        *(float4*)&g_h[(size_t)gm * HID + block_n + tx * 4] = r;
    }
}

// ---------------------------------------------------------------------------
// GEMM2: g_st[M, DIM] = g_h @ W2 + b2
// ---------------------------------------------------------------------------
__global__ __launch_bounds__(256)
void gemm2_kernel(const float* __restrict__ W2,
                  const float* __restrict__ b2)
{
    __shared__ float As[BM][BK];
    __shared__ float Bs[BK][BN];

    const int tid = threadIdx.x;
    const int tx  = tid & 15;
    const int ty  = tid >> 4;
    const int block_n = blockIdx.x * BN;
    const int block_m = blockIdx.y * BM;

    float acc[TM][TN];
#pragma unroll
    for (int i = 0; i < TM; i++)
#pragma unroll
        for (int j = 0; j < TN; j++) acc[i][j] = 0.0f;

    for (int k0 = 0; k0 < HID; k0 += BK) {
        // A tile from g_h (row-major), vectorized float4: 2 per thread
#pragma unroll
        for (int i = 0; i < 2; i++) {
            int idx4 = i * 256 + tid;          // float4 index within 128x16 tile
            int ml   = idx4 >> 2;              // /4 float4 per row
            int kl   = (idx4 & 3) * 4;
            int gm   = block_m + ml;
            float4 v = *(const float4*)&g_h[(size_t)gm * HID + k0 + kl];
            *(float4*)&As[ml][kl] = v;
        }
        // B tile from W2: 16x64
        {
            int kl = tid >> 4;
            int nl = (tid & 15) * 4;
            const float4 w = *(const float4*)&W2[(size_t)(k0 + kl) * DIM + block_n + nl];
            *(float4*)&Bs[kl][nl] = w;
        }
        __syncthreads();

#pragma unroll
        for (int k = 0; k < BK; k++) {
            float4 b4 = *(float4*)&Bs[k][tx * 4];
            float a[TM];
#pragma unroll
            for (int i = 0; i < TM; i++) a[i] = As[ty * TM + i][k];
#pragma unroll
            for (int i = 0; i < TM; i++) {
                acc[i][0] = fmaf(a[i], b4.x, acc[i][0]);
                acc[i][1] = fmaf(a[i], b4.y, acc[i][1]);
                acc[i][2] = fmaf(a[i], b4.z, acc[i][2]);
                acc[i][3] = fmaf(a[i], b4.w, acc[i][3]);
            }
        }
        __syncthreads();
    }

    const float4 bias = *(const float4*)&b2[block_n + tx * 4];
#pragma unroll
    for (int i = 0; i < TM; i++) {
        int gm = block_m + ty * TM + i;
        float4 r;
        r.x = acc[i][0] + bias.x;
        r.y = acc[i][1] + bias.y;
        r.z = acc[i][2] + bias.z;
        r.w = acc[i][3] + bias.w;
        *(float4*)&g_st[(size_t)gm * DIM + block_n + tx * 4] = r;
    }
}

// ---------------------------------------------------------------------------
// Epilogue: per row, s = 5*tanh(st[:256]); t = st[256:];
// y[2j] = x[2j]; y[2j+1] = x[2j+1]*exp(s_j) + t_j; log_det = sum(s)
// ---------------------------------------------------------------------------
__global__ __launch_bounds__(256)
void epilogue_kernel(const float* __restrict__ x,
                     float* __restrict__ out_y,
                     float* __restrict__ out_logdet)
{
    const int row = blockIdx.x;
    const int j   = threadIdx.x;   // 0..255

    const float* st = &g_st[(size_t)row * DIM];
    float s = tanhf(st[j]) * S_MAX;
    float t = st[256 + j];

    float2 x2 = *(const float2*)&x[(size_t)row * DIM + 2 * j];
    float2 y2;
    y2.x = x2.x;
    y2.y = fmaf(x2.y, expf(s), t);
    *(float2*)&out_y[(size_t)row * DIM + 2 * j] = y2;

    // block reduction of s
    float v = s;
#pragma unroll
    for (int o = 16; o > 0; o >>= 1)
        v += __shfl_down_sync(0xFFFFFFFFu, v, o);

    __shared__ float red[8];
    int lane = j & 31, warp = j >> 5;
    if (lane == 0) red[warp] = v;
    __syncthreads();
    if (j == 0) {
        float total = 0.0f;
#pragma unroll
        for (int w = 0; w < 8; w++) total += red[w];
        out_logdet[row] = total;
    }
}

extern "C" void kernel_launch(void* const* d_in, const int* in_sizes, int n_in,
                              void* d_out, int out_size)
{
    const float* x   = (const float*)d_in[0];
    const float* ctx = (const float*)d_in[1];
    const float* W1  = (const float*)d_in[2];
    const float* b1  = (const float*)d_in[3];
    const float* W2  = (const float*)d_in[4];
    const float* b2  = (const float*)d_in[5];

    float* y      = (float*)d_out;                       // B_ROWS * DIM
    float* logdet = (float*)d_out + (size_t)B_ROWS * DIM; // B_ROWS

    dim3 blk(256);
    dim3 g1(HID / BN, B_ROWS / BM);   // (32, 1024)
    dim3 g2(DIM / BN, B_ROWS / BM);   // (8, 1024)

    gemm1_kernel<<<g1, blk>>>(x, ctx, W1, b1);
    gemm2_kernel<<<g2, blk>>>(W2, b2);
    epilogue_kernel<<<B_ROWS, blk>>>(x, y, logdet);
}

// round 3
// speedup vs baseline: 3.7262x; 3.7262x over previous
#include <cuda_runtime.h>
#include <cstdint>
#include <math.h>

#define B_ROWS 131072
#define DIM    512
#define CTX    128
#define HID    2048
#define KIN    384
#define S_MAX  5.0f

// ---------------------------------------------------------------------------
// Scratch device globals (no allocations allowed)
// ---------------------------------------------------------------------------
__device__ float g_A1[(size_t)B_ROWS * KIN];   // gathered [x_even | ctx], tf32-rounded
__device__ float g_h [(size_t)B_ROWS * HID];   // relu(A1 @ W1 + b1), tf32-rounded
__device__ float g_st[(size_t)B_ROWS * DIM];   // h @ W2 + b2

// ---------------------------------------------------------------------------
// helpers
// ---------------------------------------------------------------------------
__device__ __forceinline__ uint32_t smem_to_u32(const void* p) {
    uint32_t a;
    asm("{ .reg .u64 t; cvta.to.shared.u64 t, %1; cvt.u32.u64 %0, t; }" : "=r"(a) : "l"(p));
    return a;
}
__device__ __forceinline__ float to_tf32(float v) {
    uint32_t r;
    asm("cvt.rna.tf32.f32 %0, %1;" : "=r"(r) : "f"(v));
    return __uint_as_float(r);
}
__device__ __forceinline__ uint32_t f2tf32(float v) {
    uint32_t r;
    asm("cvt.rna.tf32.f32 %0, %1;" : "=r"(r) : "f"(v));
    return r;
}
__device__ __forceinline__ void cp_async16(uint32_t saddr, const void* gptr) {
    asm volatile("cp.async.ca.shared.global [%0], [%1], 16;" :: "r"(saddr), "l"(gptr));
}
#define CP_COMMIT() asm volatile("cp.async.commit_group;" ::: "memory")
#define CP_WAIT(n)  asm volatile("cp.async.wait_group %0;" :: "n"(n) : "memory")

__device__ __forceinline__ void mma_tf32(float* d, const uint32_t* a, const uint32_t* b) {
    asm volatile(
        "mma.sync.aligned.m16n8k8.row.col.f32.tf32.tf32.f32 "
        "{%0,%1,%2,%3}, {%4,%5,%6,%7}, {%8,%9}, {%0,%1,%2,%3};\n"
        : "+f"(d[0]), "+f"(d[1]), "+f"(d[2]), "+f"(d[3])
        : "r"(a[0]), "r"(a[1]), "r"(a[2]), "r"(a[3]), "r"(b[0]), "r"(b[1]));
}

// ---------------------------------------------------------------------------
// Prep: gather even-x + context, tf32-rounded
// ---------------------------------------------------------------------------
__global__ __launch_bounds__(256)
void gather_kernel(const float* __restrict__ x, const float* __restrict__ ctx)
{
    int idx = blockIdx.x * 256 + threadIdx.x;          // over B_ROWS*96 float4s
    int b  = idx / 96;
    int k4 = idx % 96;
    float4 v;
    if (k4 < 64) {
        const float* xp = &x[(size_t)b * DIM + 8 * k4];
        v.x = xp[0]; v.y = xp[2]; v.z = xp[4]; v.w = xp[6];
    } else {
        v = *(const float4*)&ctx[(size_t)b * CTX + (k4 - 64) * 4];
    }
    v.x = to_tf32(v.x); v.y = to_tf32(v.y); v.z = to_tf32(v.z); v.w = to_tf32(v.w);
    *(float4*)&g_A1[(size_t)b * KIN + k4 * 4] = v;
}

// ---------------------------------------------------------------------------
// GEMM via mma.sync tf32. Block 128x128, 4 warps (64x64 each), BK=32,
// cp.async double buffer. A is tf32-pre-rounded in gmem; B (weights) are
// raw f32, converted to tf32 in registers after LDS.
// ---------------------------------------------------------------------------
#define LDA 36     // floats; bank(4r+k) bijective over lanes
#define LDB 136    // floats; bank(8k+n) bijective over lanes
#define ABYTES (128 * LDA * 4)          // 18432
#define BBYTES (32 * LDB * 4)           // 17408
#define BUFBYTES (ABYTES + BBYTES)      // 35840
#define GEMM_SMEM (2 * BUFBYTES)        // 71680

template<int K_TOTAL, bool RELU_ROUND>
__global__ __launch_bounds__(128)
void gemm_mma(const float* __restrict__ A, const float* __restrict__ Bw,
              const float* __restrict__ bias, float* __restrict__ C, int N)
{
    extern __shared__ char smem[];
    const uint32_t sbase = smem_to_u32(smem);
    const int tid  = threadIdx.x;
    const int lane = tid & 31;
    const int w    = tid >> 5;
    const int wm   = (w & 1) * 64;
    const int wn   = (w >> 1) * 64;
    const int gid  = lane >> 2;   // group id 0..7
    const int tig  = lane & 3;    // thread in group

    const size_t block_m = (size_t)blockIdx.y * 128;
    const int    block_n = blockIdx.x * 128;

    // per-thread load coords (fixed across stages)
    const int a_row = tid >> 3;        // +16*i
    const int a_c4  = tid & 7;         // float4 col
    const int b_k   = tid >> 5;        // +4*i
    const int b_c4  = tid & 31;        // float4 col

    float acc[4][8][4];
#pragma unroll
    for (int mi = 0; mi < 4; mi++)
#pragma unroll
        for (int ni = 0; ni < 8; ni++)
#pragma unroll
            for (int r = 0; r < 4; r++) acc[mi][ni][r] = 0.0f;

    constexpr int NS = K_TOTAL / 32;

    auto issue_tile = [&](int s, int buf) {
        const int k0 = s * 32;
        const uint32_t sA = sbase + buf * BUFBYTES;
        const uint32_t sB = sA + ABYTES;
#pragma unroll
        for (int i = 0; i < 8; i++) {
            int r = a_row + i * 16;
            cp_async16(sA + r * (LDA * 4) + a_c4 * 16,
                       &A[(block_m + r) * K_TOTAL + k0 + a_c4 * 4]);
        }
#pragma unroll
        for (int i = 0; i < 8; i++) {
            int k = b_k + i * 4;
            cp_async16(sB + k * (LDB * 4) + b_c4 * 16,
                       &Bw[(size_t)(k0 + k) * N + block_n + b_c4 * 4]);
        }
        CP_COMMIT();
    };

    issue_tile(0, 0);

    for (int s = 0; s < NS; s++) {
        const int buf = s & 1;
        if (s + 1 < NS) {
            issue_tile(s + 1, buf ^ 1);
            CP_WAIT(1);
        } else {
            CP_WAIT(0);
        }
        __syncthreads();

        const float* As = (const float*)(smem + buf * BUFBYTES);
        const float* Bs = (const float*)(smem + buf * BUFBYTES + ABYTES);

#pragma unroll
        for (int kk = 0; kk < 4; kk++) {
            const int kb = kk * 8;
            uint32_t bfr[8][2];
#pragma unroll
            for (int ni = 0; ni < 8; ni++) {
                int col = wn + ni * 8 + gid;
                bfr[ni][0] = f2tf32(Bs[(kb + tig)     * LDB + col]);
                bfr[ni][1] = f2tf32(Bs[(kb + tig + 4) * LDB + col]);
            }
#pragma unroll
            for (int mi = 0; mi < 4; mi++) {
                int r0 = wm + mi * 16 + gid;
                uint32_t a[4];
                a[0] = __float_as_uint(As[ r0      * LDA + kb + tig]);
                a[1] = __float_as_uint(As[(r0 + 8) * LDA + kb + tig]);
                a[2] = __float_as_uint(As[ r0      * LDA + kb + tig + 4]);
                a[3] = __float_as_uint(As[(r0 + 8) * LDA + kb + tig + 4]);
#pragma unroll
                for (int ni = 0; ni < 8; ni++)
                    mma_tf32(acc[mi][ni], a, bfr[ni]);
            }
        }
        __syncthreads();
    }

    // store with bias (+ optional relu + tf32 round)
#pragma unroll
    for (int ni = 0; ni < 8; ni++) {
        int col = block_n + wn + ni * 8 + tig * 2;
        float bx = __ldg(&bias[col]);
        float by = __ldg(&bias[col + 1]);
#pragma unroll
        for (int mi = 0; mi < 4; mi++) {
            size_t r = block_m + wm + mi * 16 + gid;
            float v0 = acc[mi][ni][0] + bx;
            float v1 = acc[mi][ni][1] + by;
            float v2 = acc[mi][ni][2] + bx;
            float v3 = acc[mi][ni][3] + by;
            if (RELU_ROUND) {
                v0 = to_tf32(fmaxf(v0, 0.0f));
                v1 = to_tf32(fmaxf(v1, 0.0f));
                v2 = to_tf32(fmaxf(v2, 0.0f));
                v3 = to_tf32(fmaxf(v3, 0.0f));
            }
            float2 p0 = {v0, v1};
            float2 p1 = {v2, v3};
            *(float2*)&C[ r      * N + col] = p0;
            *(float2*)&C[(r + 8) * N + col] = p1;
        }
    }
}

// ---------------------------------------------------------------------------
// Epilogue: s = 5*tanh(st[:256]); t = st[256:]; y, log_det
// ---------------------------------------------------------------------------
__global__ __launch_bounds__(256)
void epilogue_kernel(const float* __restrict__ x,
                     float* __restrict__ out_y,
                     float* __restrict__ out_logdet)
{
    const int row = blockIdx.x;
    const int j   = threadIdx.x;   // 0..255

    const float* st = &g_st[(size_t)row * DIM];
    float s = tanhf(st[j]) * S_MAX;
    float t = st[256 + j];

    float2 x2 = *(const float2*)&x[(size_t)row * DIM + 2 * j];
    float2 y2;
    y2.x = x2.x;
    y2.y = fmaf(x2.y, expf(s), t);
    *(float2*)&out_y[(size_t)row * DIM + 2 * j] = y2;

    float v = s;
#pragma unroll
    for (int o = 16; o > 0; o >>= 1)
        v += __shfl_down_sync(0xFFFFFFFFu, v, o);

    __shared__ float red[8];
    int lane = j & 31, warp = j >> 5;
    if (lane == 0) red[warp] = v;
    __syncthreads();
    if (j == 0) {
        float total = 0.0f;
#pragma unroll
        for (int wq = 0; wq < 8; wq++) total += red[wq];
        out_logdet[row] = total;
    }
}

// ---------------------------------------------------------------------------
extern "C" void kernel_launch(void* const* d_in, const int* in_sizes, int n_in,
                              void* d_out, int out_size)
{
    const float* x   = (const float*)d_in[0];
    const float* ctx = (const float*)d_in[1];
    const float* W1  = (const float*)d_in[2];
    const float* b1  = (const float*)d_in[3];
    const float* W2  = (const float*)d_in[4];
    const float* b2  = (const float*)d_in[5];

    float* y      = (float*)d_out;
    float* logdet = (float*)d_out + (size_t)B_ROWS * DIM;

    float* A1;  cudaGetSymbolAddress((void**)&A1,  g_A1);
    float* hC;  cudaGetSymbolAddress((void**)&hC,  g_h);
    float* stC; cudaGetSymbolAddress((void**)&stC, g_st);

    cudaFuncSetAttribute(gemm_mma<KIN, true>,
                         cudaFuncAttributeMaxDynamicSharedMemorySize, GEMM_SMEM);
    cudaFuncSetAttribute(gemm_mma<HID, false>,
                         cudaFuncAttributeMaxDynamicSharedMemorySize, GEMM_SMEM);

    gather_kernel<<<(B_ROWS * 96) / 256, 256>>>(x, ctx);

    gemm_mma<KIN, true><<<dim3(HID / 128, B_ROWS / 128), 128, GEMM_SMEM>>>(
        A1, W1, b1, hC, HID);

    gemm_mma<HID, false><<<dim3(DIM / 128, B_ROWS / 128), 128, GEMM_SMEM>>>(
        hC, W2, b2, stC, DIM);

    epilogue_kernel<<<B_ROWS, 256>>>(x, y, logdet);
}